// round 14
// baseline (speedup 1.0000x reference)
#include <cuda_runtime.h>
#include <math.h>

#define BB 4
#define SS 2048
#define EE 512
#define HH 8
#define HD 64
#define SCALE 0.04419417382415922f  /* 512^-0.5 (reference scales by E, not HD) */
#define ERBW 6656
#define EROFF 2056

// Scratch (static device arrays — allocation rules forbid cudaMalloc)
__device__ float    g_q [BB * HH * SS * HD];           // fp32 Q
__device__ unsigned g_kb[(size_t)BB * HH * 32 * SS];   // bf16x2-packed K [bh][d2][s]
__device__ float    g_vt[(size_t)BB * HH * SS * HD];   // tf32-bits V [bh][s][d]
__device__ unsigned g_erb[32 * ERBW];                  // bf16x2 Er [d2][EROFF+l], zero-padded

// ---------------------------------------------------------------------------
// helpers
// ---------------------------------------------------------------------------
__device__ __forceinline__ unsigned f2tf(float x) {
    unsigned r; asm("cvt.rna.tf32.f32 %0, %1;" : "=r"(r) : "f"(x)); return r;
}
__device__ __forceinline__ unsigned pk2(float hi, float lo) {
    unsigned r; asm("cvt.rn.bf16x2.f32 %0, %1, %2;" : "=r"(r) : "f"(hi), "f"(lo)); return r;
}

__device__ __forceinline__ void mma8(float4& c,
    unsigned a0, unsigned a1, unsigned a2, unsigned a3, unsigned b0, unsigned b1)
{
    asm("mma.sync.aligned.m16n8k8.row.col.f32.tf32.tf32.f32 "
        "{%0,%1,%2,%3}, {%4,%5,%6,%7}, {%8,%9}, {%0,%1,%2,%3};"
        : "+f"(c.x), "+f"(c.y), "+f"(c.z), "+f"(c.w)
        : "r"(a0), "r"(a1), "r"(a2), "r"(a3), "r"(b0), "r"(b1));
}
__device__ __forceinline__ void mma16(float4& c,
    unsigned a0, unsigned a1, unsigned a2, unsigned a3, unsigned b0, unsigned b1)
{
    asm("mma.sync.aligned.m16n8k16.row.col.f32.bf16.bf16.f32 "
        "{%0,%1,%2,%3}, {%4,%5,%6,%7}, {%8,%9}, {%0,%1,%2,%3};"
        : "+f"(c.x), "+f"(c.y), "+f"(c.z), "+f"(c.w)
        : "r"(a0), "r"(a1), "r"(a2), "r"(a3), "r"(b0), "r"(b1));
}
__device__ __forceinline__ void cpa16(float* dst, const float* src) {
    unsigned sa = (unsigned)__cvta_generic_to_shared(dst);
    asm volatile("cp.async.cg.shared.global [%0], [%1], 16;" :: "r"(sa), "l"(src));
}
#define CP_COMMIT() asm volatile("cp.async.commit_group;")
#define CP_WAIT(n)  asm volatile("cp.async.wait_group %0;" :: "n"(n))

// ---------------------------------------------------------------------------
// Kernel 0: pack Er into zero-padded bf16x2 rows [d2][EROFF + l].
// ---------------------------------------------------------------------------
__global__ void __launch_bounds__(256) erb_kernel(const float* __restrict__ Er)
{
    int idx = blockIdx.x * 256 + threadIdx.x;   // 65536 = 32 d2 x 2048 l
    int d2 = idx >> 11, l = idx & 2047;
    float2 e = *(const float2*)&Er[(size_t)l * HD + 2 * d2];
    g_erb[d2 * ERBW + EROFF + l] = pk2(e.y, e.x);
}

// ---------------------------------------------------------------------------
// Kernel 1: QKV projection, occupancy 2.
//   z=0/1 (Q/K): bf16 m16n8k16 single-pass — Q/K are consumed as bf16 anyway;
//                input rounding adds ~5.1e-4 RSS (calibrated from R7/R8 data).
//   z=2 (V): tf32 m16n8k8 single-pass (V errors hit the output linearly).
// ---------------------------------------------------------------------------
#define QKV_SMEM_BYTES (18432 * 4)

__global__ void __launch_bounds__(256, 2) qkv_kernel(
    const float* __restrict__ x, const float* __restrict__ Wq,
    const float* __restrict__ Wk, const float* __restrict__ Wv)
{
    extern __shared__ float sm[];
    const int z = blockIdx.z;
    const float* W = z == 0 ? Wq : (z == 1 ? Wk : Wv);
    const int m0 = blockIdx.y * 128, n0 = blockIdx.x * 128;
    const int tid = threadIdx.x, lane = tid & 31, warp = tid >> 5;
    const int g = lane >> 2, t = lane & 3;
    const int mw = (warp >> 2) * 64, nw = (warp & 3) * 32;

    float* Xs[2] = { sm, sm + 4608 };
    float* Ws[2] = { sm + 9216, sm + 13824 };
    const int r_ = tid >> 1, c_ = (tid & 1) * 16;
    #define STAGE(buf, k0) do { \
        cpa16(Xs[buf] + r_ * 36 + c_,      &x[(size_t)(m0 + r_) * EE + (k0) + c_]); \
        cpa16(Xs[buf] + r_ * 36 + c_ + 4,  &x[(size_t)(m0 + r_) * EE + (k0) + c_ + 4]); \
        cpa16(Xs[buf] + r_ * 36 + c_ + 8,  &x[(size_t)(m0 + r_) * EE + (k0) + c_ + 8]); \
        cpa16(Xs[buf] + r_ * 36 + c_ + 12, &x[(size_t)(m0 + r_) * EE + (k0) + c_ + 12]); \
        cpa16(Ws[buf] + r_ * 36 + c_,      &W[(size_t)(n0 + r_) * EE + (k0) + c_]); \
        cpa16(Ws[buf] + r_ * 36 + c_ + 4,  &W[(size_t)(n0 + r_) * EE + (k0) + c_ + 4]); \
        cpa16(Ws[buf] + r_ * 36 + c_ + 8,  &W[(size_t)(n0 + r_) * EE + (k0) + c_ + 8]); \
        cpa16(Ws[buf] + r_ * 36 + c_ + 12, &W[(size_t)(n0 + r_) * EE + (k0) + c_ + 12]); \
        CP_COMMIT(); \
    } while (0)

    float4 acc[4][4];
    #pragma unroll
    for (int m = 0; m < 4; m++)
        #pragma unroll
        for (int n = 0; n < 4; n++) acc[m][n] = make_float4(0.f, 0.f, 0.f, 0.f);

    STAGE(0, 0);
    for (int p = 0; p < 16; p++) {
        if (p < 15) STAGE((p + 1) & 1, (p + 1) * 32);
        if (p < 15) { CP_WAIT(1); } else { CP_WAIT(0); }
        __syncthreads();
        const float* Xb = Xs[p & 1];
        const float* Wb = Ws[p & 1];

        if (z < 2) {
            // ---- bf16 single-pass: 2 k16 steps ----
            #pragma unroll
            for (int s = 0; s < 2; s++) {
                unsigned a[4][4], b[4][2];
                #pragma unroll
                for (int m = 0; m < 4; m++) {
                    const float* r0 = &Xb[(mw + 16 * m + g) * 36 + 16 * s];
                    const float* r1 = &Xb[(mw + 16 * m + g + 8) * 36 + 16 * s];
                    float2 f0 = *(const float2*)&r0[2 * t];
                    float2 f1 = *(const float2*)&r1[2 * t];
                    float2 f2 = *(const float2*)&r0[2 * t + 8];
                    float2 f3 = *(const float2*)&r1[2 * t + 8];
                    a[m][0] = pk2(f0.y, f0.x);
                    a[m][1] = pk2(f1.y, f1.x);
                    a[m][2] = pk2(f2.y, f2.x);
                    a[m][3] = pk2(f3.y, f3.x);
                }
                #pragma unroll
                for (int n = 0; n < 4; n++) {
                    const float* w0 = &Wb[(nw + 8 * n + g) * 36 + 16 * s];
                    float2 f0 = *(const float2*)&w0[2 * t];
                    float2 f1 = *(const float2*)&w0[2 * t + 8];
                    b[n][0] = pk2(f0.y, f0.x);
                    b[n][1] = pk2(f1.y, f1.x);
                }
                #pragma unroll
                for (int m = 0; m < 4; m++)
                    #pragma unroll
                    for (int n = 0; n < 4; n++)
                        mma16(acc[m][n], a[m][0], a[m][1], a[m][2], a[m][3], b[n][0], b[n][1]);
            }
        } else {
            // ---- tf32 single-pass: 4 k8 steps ----
            #pragma unroll
            for (int s = 0; s < 4; s++) {
                unsigned a[4][4], b[4][2];
                #pragma unroll
                for (int m = 0; m < 4; m++) {
                    const float* r0 = &Xb[(mw + 16 * m + g) * 36 + 8 * s];
                    const float* r1 = &Xb[(mw + 16 * m + g + 8) * 36 + 8 * s];
                    a[m][0] = f2tf(r0[t]); a[m][1] = f2tf(r1[t]);
                    a[m][2] = f2tf(r0[t + 4]); a[m][3] = f2tf(r1[t + 4]);
                }
                #pragma unroll
                for (int n = 0; n < 4; n++) {
                    const float* w0 = &Wb[(nw + 8 * n + g) * 36 + 8 * s];
                    b[n][0] = f2tf(w0[t]); b[n][1] = f2tf(w0[t + 4]);
                }
                #pragma unroll
                for (int m = 0; m < 4; m++)
                    #pragma unroll
                    for (int n = 0; n < 4; n++)
                        mma8(acc[m][n], a[m][0], a[m][1], a[m][2], a[m][3], b[n][0], b[n][1]);
            }
        }
        __syncthreads();
    }

    #pragma unroll
    for (int m = 0; m < 4; m++) {
        int r0 = m0 + mw + 16 * m + g, r1 = r0 + 8;
        int b0_ = r0 >> 11, s0_ = r0 & 2047;
        int b1_ = r1 >> 11, s1_ = r1 & 2047;
        #pragma unroll
        for (int n = 0; n < 4; n++) {
            int col = n0 + nw + 8 * n + 2 * t;
            int h = col >> 6, d = col & 63;
            if (z == 0) {
                *(float2*)&g_q[(((size_t)b0_ * HH + h) * SS + s0_) * HD + d] = make_float2(acc[m][n].x, acc[m][n].y);
                *(float2*)&g_q[(((size_t)b1_ * HH + h) * SS + s1_) * HD + d] = make_float2(acc[m][n].z, acc[m][n].w);
            } else if (z == 1) {
                int d2 = d >> 1;
                g_kb[((size_t)(b0_ * HH + h) * 32 + d2) * SS + s0_] = pk2(acc[m][n].y, acc[m][n].x);
                g_kb[((size_t)(b1_ * HH + h) * 32 + d2) * SS + s1_] = pk2(acc[m][n].w, acc[m][n].z);
            } else {
                *(float2*)&g_vt[(((size_t)b0_ * HH + h) * SS + s0_) * HD + d] =
                    make_float2(__uint_as_float(f2tf(acc[m][n].x)), __uint_as_float(f2tf(acc[m][n].y)));
                *(float2*)&g_vt[(((size_t)b1_ * HH + h) * SS + s1_) * HD + d] =
                    make_float2(__uint_as_float(f2tf(acc[m][n].z)), __uint_as_float(f2tf(acc[m][n].w)));
            }
        }
    }
}

// ---------------------------------------------------------------------------
// Kernel 2: flash attention with relative-position skew — 64-row CTAs,
// 128 threads, 2 CTAs/SM. Staging is pure copy (operands pre-packed).
//
// Srel[i,j] = q_i . Er[S-1-(i-j)]  (j<=i) | 0 (j=i+1) | q_{i+1} . Er[j-i-2] (j>=i+2)
//
// S, R1, R2: bf16 m16n8k16 single-pass.  PV: tf32 m16n8k8 single-pass.
// Measured at the sm_103a legacy-mma issue floor (~32 cyc/SMSP/instr).
// ---------------------------------------------------------------------------
#define QP 68
#define KP2 72
#define VP 72
#define WP2 136
#define RP 84
#define SM_Q  0
#define SM_K  4420
#define SM_V  6724
#define SM_W1 11332
#define SM_W2 15684
#define SM_R  20036
#define SM_TOT_FLOATS 25412
#define SMEM_BYTES (SM_TOT_FLOATS * 4)   /* 101648 B -> 2 CTAs/SM */

__global__ void __launch_bounds__(128, 2) attn_kernel(float* __restrict__ out)
{
    extern __shared__ float sm[];
    float* Qs   = sm + SM_Q;
    unsigned* Khs = (unsigned*)(sm + SM_K);
    float* Vs   = sm + SM_V;
    unsigned* W1h = (unsigned*)(sm + SM_W1);
    unsigned* W2h = (unsigned*)(sm + SM_W2);
    float* Rscr = sm + SM_R;
    unsigned* Pb = (unsigned*)sm;
    const unsigned* Vsu = (const unsigned*)Vs;

    const int tid  = threadIdx.x;
    const int lane = tid & 31;
    const int warp = tid >> 5;
    const int g = lane >> 2;
    const int t = lane & 3;
    const int rbase = warp * 16;

    const int bh = blockIdx.y;
    const int i0 = blockIdx.x * 64;

    const float* qb0 = g_q + (size_t)bh * SS * HD;
    const unsigned* kbb = g_kb + (size_t)bh * 32 * SS;
    const float* vb0 = g_vt + (size_t)bh * SS * HD;

    for (int idx = tid; idx < 65 * 16; idx += 128) {
        int r = idx >> 4, dq = (idx & 15) * 4;
        float4 v = make_float4(0.f, 0.f, 0.f, 0.f);
        int gi = i0 + r;
        if (gi < SS) v = *(const float4*)&qb0[(size_t)gi * HD + dq];
        *(float4*)&Qs[r * QP + dq] = v;
    }
    __syncthreads();

    unsigned aq[4][4], aq2[4][4];
    {
        const float* r0 = &Qs[(rbase + g) * QP];
        const float* r1 = &Qs[(rbase + g + 8) * QP];
        const float* s0 = &Qs[(rbase + g + 1) * QP];
        const float* s1 = &Qs[(rbase + g + 9) * QP];
        #pragma unroll
        for (int s = 0; s < 4; s++) {
            float2 f0 = *(const float2*)&r0[16 * s + 2 * t];
            float2 f1 = *(const float2*)&r1[16 * s + 2 * t];
            float2 f2 = *(const float2*)&r0[16 * s + 2 * t + 8];
            float2 f3 = *(const float2*)&r1[16 * s + 2 * t + 8];
            aq[s][0] = pk2(f0.y, f0.x);
            aq[s][1] = pk2(f1.y, f1.x);
            aq[s][2] = pk2(f2.y, f2.x);
            aq[s][3] = pk2(f3.y, f3.x);
            float2 h0 = *(const float2*)&s0[16 * s + 2 * t];
            float2 h1 = *(const float2*)&s1[16 * s + 2 * t];
            float2 h2 = *(const float2*)&s0[16 * s + 2 * t + 8];
            float2 h3 = *(const float2*)&s1[16 * s + 2 * t + 8];
            aq2[s][0] = pk2(h0.y, h0.x);
            aq2[s][1] = pk2(h1.y, h1.x);
            aq2[s][2] = pk2(h2.y, h2.x);
            aq2[s][3] = pk2(h3.y, h3.x);
        }
    }
    __syncthreads();  // frag build done before Pb overwrites Qs

    float4 Oacc[8];
    #pragma unroll
    for (int n = 0; n < 8; n++) Oacc[n] = make_float4(0.f, 0.f, 0.f, 0.f);
    float m0r = -1e30f, m1r = -1e30f, l0r = 0.f, l1r = 0.f;

    const float* rp0 = &Rscr[(rbase + g) * RP];
    const float* rp1 = &Rscr[(rbase + g + 8) * RP];
    float* wr0 = &Rscr[(rbase + g) * RP + 2 * t];
    float* wr1 = &Rscr[(rbase + g + 8) * RP + 2 * t];
    unsigned* Pb0 = Pb + (rbase + g) * QP;
    unsigned* Pb1 = Pb + (rbase + g + 8) * QP;
    const int off1w = 48 - rbase;
    const int tlb = 2 * t + 15 - g;
    const int diffb = (2 * t) - (i0 + rbase + g);

    for (int j0 = 0; j0 < SS; j0 += 64) {
        __syncthreads();

        const bool need1 = (j0 <= i0 + 63);
        const bool need2 = (j0 + 63 >= i0 + 2);
        const int L1 = SS - 64 - i0 + j0;
        const int L2 = j0 - i0 - 65;

        // ---- staging: pure copies (operands pre-packed) ----
        #pragma unroll
        for (int ii = 0; ii < 16; ii++) {
            int idx = tid + ii * 128;
            int d2 = idx >> 6, j = idx & 63;
            Khs[d2 * KP2 + j] = kbb[(size_t)d2 * SS + j0 + j];
        }
        #pragma unroll
        for (int ii = 0; ii < 8; ii++) {
            int idx = tid + ii * 128;
            int j = idx >> 4, dq = (idx & 15) * 4;
            *(float4*)&Vs[j * VP + dq] = *(const float4*)&vb0[(size_t)(j0 + j) * HD + dq];
        }
        if (need1) {
            #pragma unroll
            for (int ii = 0; ii < 32; ii++) {
                int idx = tid + ii * 128;
                int d2 = idx >> 7, tl = idx & 127;
                W1h[d2 * WP2 + tl] = g_erb[d2 * ERBW + EROFF + L1 + tl];
            }
        }
        if (need2) {
            #pragma unroll
            for (int ii = 0; ii < 32; ii++) {
                int idx = tid + ii * 128;
                int d2 = idx >> 7, tl = idx & 127;
                W2h[d2 * WP2 + tl] = g_erb[d2 * ERBW + EROFF + L2 + tl];
            }
        }
        __syncthreads();

        // ---- S = Q K^T (bf16, 32 mma) ----
        float4 sacc[8];
        #pragma unroll
        for (int n = 0; n < 8; n++) {
            float4 c = make_float4(0.f, 0.f, 0.f, 0.f);
            #pragma unroll
            for (int s = 0; s < 4; s++) {
                unsigned b0 = Khs[(8 * s + t) * KP2 + 8 * n + g];
                unsigned b1 = Khs[(8 * s + t + 4) * KP2 + 8 * n + g];
                mma16(c, aq[s][0], aq[s][1], aq[s][2], aq[s][3], b0, b1);
            }
            sacc[n] = c;
        }

        const bool wneed1 = (j0 <= i0 + rbase + 15);
        const bool wneed2 = (j0 + 63 >= i0 + rbase + 2);

        if (wneed1) {
            #pragma unroll
            for (int n = 0; n < 10; n++) {
                float4 c = make_float4(0.f, 0.f, 0.f, 0.f);
                #pragma unroll
                for (int s = 0; s < 4; s++) {
                    unsigned b0 = W1h[(8 * s + t) * WP2 + off1w + 8 * n + g];
                    unsigned b1 = W1h[(8 * s + t + 4) * WP2 + off1w + 8 * n + g];
                    mma16(c, aq[s][0], aq[s][1], aq[s][2], aq[s][3], b0, b1);
                }
                wr0[8 * n] = c.x; wr0[8 * n + 1] = c.y;
                wr1[8 * n] = c.z; wr1[8 * n + 1] = c.w;
            }
            __syncwarp();
            #pragma unroll
            for (int n = 0; n < 8; n++) {
                int d00 = diffb + j0 + 8 * n;
                int tl = tlb + 8 * n;
                if (d00 <= 0)     sacc[n].x += rp0[tl];
                if (d00 + 1 <= 0) sacc[n].y += rp0[tl + 1];
                if (d00 - 8 <= 0) sacc[n].z += rp1[tl - 8];
                if (d00 - 7 <= 0) sacc[n].w += rp1[tl - 7];
            }
            __syncwarp();
        }
        if (wneed2) {
            #pragma unroll
            for (int n = 0; n < 10; n++) {
                float4 c = make_float4(0.f, 0.f, 0.f, 0.f);
                #pragma unroll
                for (int s = 0; s < 4; s++) {
                    unsigned b0 = W2h[(8 * s + t) * WP2 + off1w + 8 * n + g];
                    unsigned b1 = W2h[(8 * s + t + 4) * WP2 + off1w + 8 * n + g];
                    mma16(c, aq2[s][0], aq2[s][1], aq2[s][2], aq2[s][3], b0, b1);
                }
                wr0[8 * n] = c.x; wr0[8 * n + 1] = c.y;
                wr1[8 * n] = c.z; wr1[8 * n + 1] = c.w;
            }
            __syncwarp();
            #pragma unroll
            for (int n = 0; n < 8; n++) {
                int d00 = diffb + j0 + 8 * n;
                int tl = tlb + 8 * n;
                if (d00 >= 2)     sacc[n].x += rp0[tl];
                if (d00 + 1 >= 2) sacc[n].y += rp0[tl + 1];
                if (d00 - 8 >= 2) sacc[n].z += rp1[tl - 8];
                if (d00 - 7 >= 2) sacc[n].w += rp1[tl - 7];
            }
            __syncwarp();
        }

        // ---- scale + online softmax ----
        float mx0 = -1e30f, mx1 = -1e30f;
        #pragma unroll
        for (int n = 0; n < 8; n++) {
            sacc[n].x *= SCALE; sacc[n].y *= SCALE;
            sacc[n].z *= SCALE; sacc[n].w *= SCALE;
            mx0 = fmaxf(mx0, fmaxf(sacc[n].x, sacc[n].y));
            mx1 = fmaxf(mx1, fmaxf(sacc[n].z, sacc[n].w));
        }
        #pragma unroll
        for (int off = 1; off <= 2; off <<= 1) {
            mx0 = fmaxf(mx0, __shfl_xor_sync(0xffffffffu, mx0, off));
            mx1 = fmaxf(mx1, __shfl_xor_sync(0xffffffffu, mx1, off));
        }
        float mn0 = fmaxf(m0r, mx0), mn1 = fmaxf(m1r, mx1);
        float c0 = __expf(m0r - mn0), c1 = __expf(m1r - mn1);
        float rs0 = 0.f, rs1 = 0.f;
        #pragma unroll
        for (int n = 0; n < 8; n++) {
            sacc[n].x = __expf(sacc[n].x - mn0);
            sacc[n].y = __expf(sacc[n].y - mn0);
            sacc[n].z = __expf(sacc[n].z - mn1);
            sacc[n].w = __expf(sacc[n].w - mn1);
            rs0 += sacc[n].x + sacc[n].y;
            rs1 += sacc[n].z + sacc[n].w;
        }
        #pragma unroll
        for (int off = 1; off <= 2; off <<= 1) {
            rs0 += __shfl_xor_sync(0xffffffffu, rs0, off);
            rs1 += __shfl_xor_sync(0xffffffffu, rs1, off);
        }
        l0r = l0r * c0 + rs0;  m0r = mn0;
        l1r = l1r * c1 + rs1;  m1r = mn1;
        #pragma unroll
        for (int n = 0; n < 8; n++) {
            Oacc[n].x *= c0; Oacc[n].y *= c0;
            Oacc[n].z *= c1; Oacc[n].w *= c1;
        }

        // ---- stage P (tf32 bits, warp-private rows) ----
        #pragma unroll
        for (int n = 0; n < 8; n++) {
            Pb0[8 * n + 2 * t]     = f2tf(sacc[n].x);
            Pb0[8 * n + 2 * t + 1] = f2tf(sacc[n].y);
            Pb1[8 * n + 2 * t]     = f2tf(sacc[n].z);
            Pb1[8 * n + 2 * t + 1] = f2tf(sacc[n].w);
        }
        __syncwarp();

        // ---- O += P V  (tf32 single-pass, 64 mma) ----
        #pragma unroll
        for (int sp = 0; sp < 8; sp++) {
            unsigned a0 = Pb0[8 * sp + t];
            unsigned a1 = Pb1[8 * sp + t];
            unsigned a2 = Pb0[8 * sp + t + 4];
            unsigned a3 = Pb1[8 * sp + t + 4];
            #pragma unroll
            for (int n = 0; n < 8; n++) {
                unsigned b0 = Vsu[(8 * sp + t) * VP + 8 * n + g];
                unsigned b1 = Vsu[(8 * sp + t + 4) * VP + 8 * n + g];
                mma8(Oacc[n], a0, a1, a2, a3, b0, b1);
            }
        }
        __syncwarp();
    }

    // ---- normalize + write out [b][s][h*64+d] ----
    const int b_ = bh >> 3, h = bh & 7;
    const float inv0 = 1.0f / l0r, inv1 = 1.0f / l1r;
    float* op0 = out + ((size_t)b_ * SS + (i0 + rbase + g)) * EE + h * HD;
    float* op1 = out + ((size_t)b_ * SS + (i0 + rbase + g + 8)) * EE + h * HD;
    #pragma unroll
    for (int n = 0; n < 8; n++) {
        *(float2*)&op0[8 * n + 2 * t] = make_float2(Oacc[n].x * inv0, Oacc[n].y * inv0);
        *(float2*)&op1[8 * n + 2 * t] = make_float2(Oacc[n].z * inv1, Oacc[n].w * inv1);
    }
}

// ---------------------------------------------------------------------------
// Kernel 3: in-place LayerNorm — one warp per row, pure shuffle reduction.
// ---------------------------------------------------------------------------
__global__ void __launch_bounds__(256) ln_kernel(
    float* __restrict__ out,
    const float* __restrict__ gamma,
    const float* __restrict__ beta)
{
    const int tid = threadIdx.x;
    const int lane = tid & 31, warp = tid >> 5;
    const int row = blockIdx.x * 8 + warp;
    float* p = out + (size_t)row * EE;

    float4 v[4];
    float s = 0.f, q = 0.f;
    #pragma unroll
    for (int k = 0; k < 4; k++) {
        v[k] = *(const float4*)&p[k * 128 + lane * 4];
        s += v[k].x + v[k].y + v[k].z + v[k].w;
        q += v[k].x * v[k].x + v[k].y * v[k].y + v[k].z * v[k].z + v[k].w * v[k].w;
    }
    #pragma unroll
    for (int off = 16; off > 0; off >>= 1) {
        s += __shfl_xor_sync(0xffffffffu, s, off);
        q += __shfl_xor_sync(0xffffffffu, q, off);
    }

    float mu = s * (1.0f / EE);
    float var = q * (1.0f / EE) - mu * mu;
    float inv = rsqrtf(var + 1e-5f);
    #pragma unroll
    for (int k = 0; k < 4; k++) {
        float4 gm = *(const float4*)&gamma[k * 128 + lane * 4];
        float4 bt = *(const float4*)&beta[k * 128 + lane * 4];
        float4 r;
        r.x = (v[k].x - mu) * inv * gm.x + bt.x;
        r.y = (v[k].y - mu) * inv * gm.y + bt.y;
        r.z = (v[k].z - mu) * inv * gm.z + bt.z;
        r.w = (v[k].w - mu) * inv * gm.w + bt.w;
        *(float4*)&p[k * 128 + lane * 4] = r;
    }
}

// ---------------------------------------------------------------------------
extern "C" void kernel_launch(void* const* d_in, const int* in_sizes, int n_in,
                              void* d_out, int out_size)
{
    const float* x     = (const float*)d_in[0];
    const float* Wq    = (const float*)d_in[1];
    const float* Wk    = (const float*)d_in[2];
    const float* Wv    = (const float*)d_in[3];
    const float* Er    = (const float*)d_in[4];
    const float* gamma = (const float*)d_in[5];
    const float* beta  = (const float*)d_in[6];
    float* out = (float*)d_out;

    cudaFuncSetAttribute(qkv_kernel, cudaFuncAttributeMaxDynamicSharedMemorySize, QKV_SMEM_BYTES);
    cudaFuncSetAttribute(attn_kernel, cudaFuncAttributeMaxDynamicSharedMemorySize, SMEM_BYTES);

    erb_kernel<<<256, 256>>>(Er);
    qkv_kernel<<<dim3(EE / 128, (BB * SS) / 128, 3), 256, QKV_SMEM_BYTES>>>(x, Wq, Wk, Wv);
    attn_kernel<<<dim3(SS / 64, BB * HH), 128, SMEM_BYTES>>>(out);
    ln_kernel<<<BB * SS / 8, 256>>>(out, gamma, beta);
}

// round 16
// speedup vs baseline: 1.0104x; 1.0104x over previous
#include <cuda_runtime.h>
#include <math.h>

#define BB 4
#define SS 2048
#define EE 512
#define HH 8
#define HD 64
#define SCALE 0.04419417382415922f  /* 512^-0.5 (reference scales by E, not HD) */
#define ERBW 6656
#define EROFF 2056

// Scratch (static device arrays — allocation rules forbid cudaMalloc)
__device__ float    g_q [BB * HH * SS * HD];           // fp32 Q
__device__ unsigned g_kb[(size_t)BB * HH * 32 * SS];   // bf16x2-packed K [bh][d2][s]
__device__ float    g_vt[(size_t)BB * HH * SS * HD];   // tf32-bits V [bh][s][d]
__device__ unsigned g_erb[32 * ERBW];                  // bf16x2 Er [d2][EROFF+l], zero-padded

// ---------------------------------------------------------------------------
// helpers
// ---------------------------------------------------------------------------
__device__ __forceinline__ unsigned f2tf(float x) {
    unsigned r; asm("cvt.rna.tf32.f32 %0, %1;" : "=r"(r) : "f"(x)); return r;
}
__device__ __forceinline__ unsigned pk2(float hi, float lo) {
    unsigned r; asm("cvt.rn.bf16x2.f32 %0, %1, %2;" : "=r"(r) : "f"(hi), "f"(lo)); return r;
}

__device__ __forceinline__ void mma8(float4& c,
    unsigned a0, unsigned a1, unsigned a2, unsigned a3, unsigned b0, unsigned b1)
{
    asm("mma.sync.aligned.m16n8k8.row.col.f32.tf32.tf32.f32 "
        "{%0,%1,%2,%3}, {%4,%5,%6,%7}, {%8,%9}, {%0,%1,%2,%3};"
        : "+f"(c.x), "+f"(c.y), "+f"(c.z), "+f"(c.w)
        : "r"(a0), "r"(a1), "r"(a2), "r"(a3), "r"(b0), "r"(b1));
}
__device__ __forceinline__ void mma16(float4& c,
    unsigned a0, unsigned a1, unsigned a2, unsigned a3, unsigned b0, unsigned b1)
{
    asm("mma.sync.aligned.m16n8k16.row.col.f32.bf16.bf16.f32 "
        "{%0,%1,%2,%3}, {%4,%5,%6,%7}, {%8,%9}, {%0,%1,%2,%3};"
        : "+f"(c.x), "+f"(c.y), "+f"(c.z), "+f"(c.w)
        : "r"(a0), "r"(a1), "r"(a2), "r"(a3), "r"(b0), "r"(b1));
}
__device__ __forceinline__ void cpa16(float* dst, const float* src) {
    unsigned sa = (unsigned)__cvta_generic_to_shared(dst);
    asm volatile("cp.async.cg.shared.global [%0], [%1], 16;" :: "r"(sa), "l"(src));
}
#define CP_COMMIT() asm volatile("cp.async.commit_group;")
#define CP_WAIT(n)  asm volatile("cp.async.wait_group %0;" :: "n"(n))

// ---------------------------------------------------------------------------
// Kernel 1: QKV projection + Er packing, occupancy 2.
//   z=0: Q fp32 [bh][s][d]   (tf32 single-pass m16n8k8)
//   z=1: K packed bf16x2 [bh][d2][s]
//   z=2: V tf32-bits [bh][s][d]
//   z=3: pack Er — the z-slice has 4x64=256 CTAs x 256 threads = exactly
//        65536 threads = one Er element per thread (idx<=65535, d2<=31).
// ---------------------------------------------------------------------------
#define QKV_SMEM_BYTES (18432 * 4)

__global__ void __launch_bounds__(256, 2) qkv_kernel(
    const float* __restrict__ x, const float* __restrict__ Wq,
    const float* __restrict__ Wk, const float* __restrict__ Wv,
    const float* __restrict__ Er)
{
    extern __shared__ float sm[];
    const int z = blockIdx.z;
    const int tid = threadIdx.x;

    if (z == 3) {
        int idx = (blockIdx.y * 4 + blockIdx.x) * 256 + tid;   // 0..65535
        int d2 = idx >> 11, l = idx & 2047;
        float2 e = *(const float2*)&Er[(size_t)l * HD + 2 * d2];
        g_erb[d2 * ERBW + EROFF + l] = pk2(e.y, e.x);
        return;
    }

    const float* W = z == 0 ? Wq : (z == 1 ? Wk : Wv);
    const int m0 = blockIdx.y * 128, n0 = blockIdx.x * 128;
    const int lane = tid & 31, warp = tid >> 5;
    const int g = lane >> 2, t = lane & 3;
    const int mw = (warp >> 2) * 64, nw = (warp & 3) * 32;

    float* Xs[2] = { sm, sm + 4608 };
    float* Ws[2] = { sm + 9216, sm + 13824 };
    const int r_ = tid >> 1, c_ = (tid & 1) * 16;
    #define STAGE(buf, k0) do { \
        cpa16(Xs[buf] + r_ * 36 + c_,      &x[(size_t)(m0 + r_) * EE + (k0) + c_]); \
        cpa16(Xs[buf] + r_ * 36 + c_ + 4,  &x[(size_t)(m0 + r_) * EE + (k0) + c_ + 4]); \
        cpa16(Xs[buf] + r_ * 36 + c_ + 8,  &x[(size_t)(m0 + r_) * EE + (k0) + c_ + 8]); \
        cpa16(Xs[buf] + r_ * 36 + c_ + 12, &x[(size_t)(m0 + r_) * EE + (k0) + c_ + 12]); \
        cpa16(Ws[buf] + r_ * 36 + c_,      &W[(size_t)(n0 + r_) * EE + (k0) + c_]); \
        cpa16(Ws[buf] + r_ * 36 + c_ + 4,  &W[(size_t)(n0 + r_) * EE + (k0) + c_ + 4]); \
        cpa16(Ws[buf] + r_ * 36 + c_ + 8,  &W[(size_t)(n0 + r_) * EE + (k0) + c_ + 8]); \
        cpa16(Ws[buf] + r_ * 36 + c_ + 12, &W[(size_t)(n0 + r_) * EE + (k0) + c_ + 12]); \
        CP_COMMIT(); \
    } while (0)

    float4 acc[4][4];
    #pragma unroll
    for (int m = 0; m < 4; m++)
        #pragma unroll
        for (int n = 0; n < 4; n++) acc[m][n] = make_float4(0.f, 0.f, 0.f, 0.f);

    STAGE(0, 0);
    for (int p = 0; p < 16; p++) {
        if (p < 15) STAGE((p + 1) & 1, (p + 1) * 32);
        if (p < 15) { CP_WAIT(1); } else { CP_WAIT(0); }
        __syncthreads();
        const float* Xb = Xs[p & 1];
        const float* Wb = Ws[p & 1];
        #pragma unroll
        for (int s = 0; s < 4; s++) {
            unsigned a[4][4], b[4][2];
            #pragma unroll
            for (int m = 0; m < 4; m++) {
                const float* r0 = &Xb[(mw + 16 * m + g) * 36 + 8 * s];
                const float* r1 = &Xb[(mw + 16 * m + g + 8) * 36 + 8 * s];
                a[m][0] = f2tf(r0[t]); a[m][1] = f2tf(r1[t]);
                a[m][2] = f2tf(r0[t + 4]); a[m][3] = f2tf(r1[t + 4]);
            }
            #pragma unroll
            for (int n = 0; n < 4; n++) {
                const float* w0 = &Wb[(nw + 8 * n + g) * 36 + 8 * s];
                b[n][0] = f2tf(w0[t]); b[n][1] = f2tf(w0[t + 4]);
            }
            #pragma unroll
            for (int m = 0; m < 4; m++)
                #pragma unroll
                for (int n = 0; n < 4; n++)
                    mma8(acc[m][n], a[m][0], a[m][1], a[m][2], a[m][3], b[n][0], b[n][1]);
        }
        __syncthreads();
    }

    #pragma unroll
    for (int m = 0; m < 4; m++) {
        int r0 = m0 + mw + 16 * m + g, r1 = r0 + 8;
        int b0_ = r0 >> 11, s0_ = r0 & 2047;
        int b1_ = r1 >> 11, s1_ = r1 & 2047;
        #pragma unroll
        for (int n = 0; n < 4; n++) {
            int col = n0 + nw + 8 * n + 2 * t;
            int h = col >> 6, d = col & 63;
            if (z == 0) {
                *(float2*)&g_q[(((size_t)b0_ * HH + h) * SS + s0_) * HD + d] = make_float2(acc[m][n].x, acc[m][n].y);
                *(float2*)&g_q[(((size_t)b1_ * HH + h) * SS + s1_) * HD + d] = make_float2(acc[m][n].z, acc[m][n].w);
            } else if (z == 1) {
                int d2 = d >> 1;
                g_kb[((size_t)(b0_ * HH + h) * 32 + d2) * SS + s0_] = pk2(acc[m][n].y, acc[m][n].x);
                g_kb[((size_t)(b1_ * HH + h) * 32 + d2) * SS + s1_] = pk2(acc[m][n].w, acc[m][n].z);
            } else {
                *(float2*)&g_vt[(((size_t)b0_ * HH + h) * SS + s0_) * HD + d] =
                    make_float2(__uint_as_float(f2tf(acc[m][n].x)), __uint_as_float(f2tf(acc[m][n].y)));
                *(float2*)&g_vt[(((size_t)b1_ * HH + h) * SS + s1_) * HD + d] =
                    make_float2(__uint_as_float(f2tf(acc[m][n].z)), __uint_as_float(f2tf(acc[m][n].w)));
            }
        }
    }
}

// ---------------------------------------------------------------------------
// Kernel 2: flash attention with relative-position skew — 64-row CTAs,
// 128 threads, 2 CTAs/SM. Staging is pure copy (operands pre-packed).
//
// Srel[i,j] = q_i . Er[S-1-(i-j)]  (j<=i) | 0 (j=i+1) | q_{i+1} . Er[j-i-2] (j>=i+2)
//
// S, R1, R2: bf16 m16n8k16 single-pass.  PV: tf32 m16n8k8 single-pass.
// Measured at the sm_103a legacy-mma issue floor (~32 cyc/SMSP/instr).
// ---------------------------------------------------------------------------
#define QP 68
#define KP2 72
#define VP 72
#define WP2 136
#define RP 84
#define SM_Q  0
#define SM_K  4420
#define SM_V  6724
#define SM_W1 11332
#define SM_W2 15684
#define SM_R  20036
#define SM_TOT_FLOATS 25412
#define SMEM_BYTES (SM_TOT_FLOATS * 4)   /* 101648 B -> 2 CTAs/SM */

__global__ void __launch_bounds__(128, 2) attn_kernel(float* __restrict__ out)
{
    extern __shared__ float sm[];
    float* Qs   = sm + SM_Q;
    unsigned* Khs = (unsigned*)(sm + SM_K);
    float* Vs   = sm + SM_V;
    unsigned* W1h = (unsigned*)(sm + SM_W1);
    unsigned* W2h = (unsigned*)(sm + SM_W2);
    float* Rscr = sm + SM_R;
    unsigned* Pb = (unsigned*)sm;
    const unsigned* Vsu = (const unsigned*)Vs;

    const int tid  = threadIdx.x;
    const int lane = tid & 31;
    const int warp = tid >> 5;
    const int g = lane >> 2;
    const int t = lane & 3;
    const int rbase = warp * 16;

    const int bh = blockIdx.y;
    const int i0 = blockIdx.x * 64;

    const float* qb0 = g_q + (size_t)bh * SS * HD;
    const unsigned* kbb = g_kb + (size_t)bh * 32 * SS;
    const float* vb0 = g_vt + (size_t)bh * SS * HD;

    for (int idx = tid; idx < 65 * 16; idx += 128) {
        int r = idx >> 4, dq = (idx & 15) * 4;
        float4 v = make_float4(0.f, 0.f, 0.f, 0.f);
        int gi = i0 + r;
        if (gi < SS) v = *(const float4*)&qb0[(size_t)gi * HD + dq];
        *(float4*)&Qs[r * QP + dq] = v;
    }
    __syncthreads();

    unsigned aq[4][4], aq2[4][4];
    {
        const float* r0 = &Qs[(rbase + g) * QP];
        const float* r1 = &Qs[(rbase + g + 8) * QP];
        const float* s0 = &Qs[(rbase + g + 1) * QP];
        const float* s1 = &Qs[(rbase + g + 9) * QP];
        #pragma unroll
        for (int s = 0; s < 4; s++) {
            float2 f0 = *(const float2*)&r0[16 * s + 2 * t];
            float2 f1 = *(const float2*)&r1[16 * s + 2 * t];
            float2 f2 = *(const float2*)&r0[16 * s + 2 * t + 8];
            float2 f3 = *(const float2*)&r1[16 * s + 2 * t + 8];
            aq[s][0] = pk2(f0.y, f0.x);
            aq[s][1] = pk2(f1.y, f1.x);
            aq[s][2] = pk2(f2.y, f2.x);
            aq[s][3] = pk2(f3.y, f3.x);
            float2 h0 = *(const float2*)&s0[16 * s + 2 * t];
            float2 h1 = *(const float2*)&s1[16 * s + 2 * t];
            float2 h2 = *(const float2*)&s0[16 * s + 2 * t + 8];
            float2 h3 = *(const float2*)&s1[16 * s + 2 * t + 8];
            aq2[s][0] = pk2(h0.y, h0.x);
            aq2[s][1] = pk2(h1.y, h1.x);
            aq2[s][2] = pk2(h2.y, h2.x);
            aq2[s][3] = pk2(h3.y, h3.x);
        }
    }
    __syncthreads();  // frag build done before Pb overwrites Qs

    float4 Oacc[8];
    #pragma unroll
    for (int n = 0; n < 8; n++) Oacc[n] = make_float4(0.f, 0.f, 0.f, 0.f);
    float m0r = -1e30f, m1r = -1e30f, l0r = 0.f, l1r = 0.f;

    const float* rp0 = &Rscr[(rbase + g) * RP];
    const float* rp1 = &Rscr[(rbase + g + 8) * RP];
    float* wr0 = &Rscr[(rbase + g) * RP + 2 * t];
    float* wr1 = &Rscr[(rbase + g + 8) * RP + 2 * t];
    unsigned* Pb0 = Pb + (rbase + g) * QP;
    unsigned* Pb1 = Pb + (rbase + g + 8) * QP;
    const int off1w = 48 - rbase;
    const int tlb = 2 * t + 15 - g;
    const int diffb = (2 * t) - (i0 + rbase + g);

    for (int j0 = 0; j0 < SS; j0 += 64) {
        __syncthreads();

        const bool need1 = (j0 <= i0 + 63);
        const bool need2 = (j0 + 63 >= i0 + 2);
        const int L1 = SS - 64 - i0 + j0;
        const int L2 = j0 - i0 - 65;

        // ---- staging: pure copies (operands pre-packed) ----
        #pragma unroll
        for (int ii = 0; ii < 16; ii++) {
            int idx = tid + ii * 128;
            int d2 = idx >> 6, j = idx & 63;
            Khs[d2 * KP2 + j] = kbb[(size_t)d2 * SS + j0 + j];
        }
        #pragma unroll
        for (int ii = 0; ii < 8; ii++) {
            int idx = tid + ii * 128;
            int j = idx >> 4, dq = (idx & 15) * 4;
            *(float4*)&Vs[j * VP + dq] = *(const float4*)&vb0[(size_t)(j0 + j) * HD + dq];
        }
        if (need1) {
            #pragma unroll
            for (int ii = 0; ii < 32; ii++) {
                int idx = tid + ii * 128;
                int d2 = idx >> 7, tl = idx & 127;
                W1h[d2 * WP2 + tl] = g_erb[d2 * ERBW + EROFF + L1 + tl];
            }
        }
        if (need2) {
            #pragma unroll
            for (int ii = 0; ii < 32; ii++) {
                int idx = tid + ii * 128;
                int d2 = idx >> 7, tl = idx & 127;
                W2h[d2 * WP2 + tl] = g_erb[d2 * ERBW + EROFF + L2 + tl];
            }
        }
        __syncthreads();

        // ---- S = Q K^T (bf16, 32 mma) ----
        float4 sacc[8];
        #pragma unroll
        for (int n = 0; n < 8; n++) {
            float4 c = make_float4(0.f, 0.f, 0.f, 0.f);
            #pragma unroll
            for (int s = 0; s < 4; s++) {
                unsigned b0 = Khs[(8 * s + t) * KP2 + 8 * n + g];
                unsigned b1 = Khs[(8 * s + t + 4) * KP2 + 8 * n + g];
                mma16(c, aq[s][0], aq[s][1], aq[s][2], aq[s][3], b0, b1);
            }
            sacc[n] = c;
        }

        const bool wneed1 = (j0 <= i0 + rbase + 15);
        const bool wneed2 = (j0 + 63 >= i0 + rbase + 2);

        if (wneed1) {
            #pragma unroll
            for (int n = 0; n < 10; n++) {
                float4 c = make_float4(0.f, 0.f, 0.f, 0.f);
                #pragma unroll
                for (int s = 0; s < 4; s++) {
                    unsigned b0 = W1h[(8 * s + t) * WP2 + off1w + 8 * n + g];
                    unsigned b1 = W1h[(8 * s + t + 4) * WP2 + off1w + 8 * n + g];
                    mma16(c, aq[s][0], aq[s][1], aq[s][2], aq[s][3], b0, b1);
                }
                wr0[8 * n] = c.x; wr0[8 * n + 1] = c.y;
                wr1[8 * n] = c.z; wr1[8 * n + 1] = c.w;
            }
            __syncwarp();
            #pragma unroll
            for (int n = 0; n < 8; n++) {
                int d00 = diffb + j0 + 8 * n;
                int tl = tlb + 8 * n;
                if (d00 <= 0)     sacc[n].x += rp0[tl];
                if (d00 + 1 <= 0) sacc[n].y += rp0[tl + 1];
                if (d00 - 8 <= 0) sacc[n].z += rp1[tl - 8];
                if (d00 - 7 <= 0) sacc[n].w += rp1[tl - 7];
            }
            __syncwarp();
        }
        if (wneed2) {
            #pragma unroll
            for (int n = 0; n < 10; n++) {
                float4 c = make_float4(0.f, 0.f, 0.f, 0.f);
                #pragma unroll
                for (int s = 0; s < 4; s++) {
                    unsigned b0 = W2h[(8 * s + t) * WP2 + off1w + 8 * n + g];
                    unsigned b1 = W2h[(8 * s + t + 4) * WP2 + off1w + 8 * n + g];
                    mma16(c, aq2[s][0], aq2[s][1], aq2[s][2], aq2[s][3], b0, b1);
                }
                wr0[8 * n] = c.x; wr0[8 * n + 1] = c.y;
                wr1[8 * n] = c.z; wr1[8 * n + 1] = c.w;
            }
            __syncwarp();
            #pragma unroll
            for (int n = 0; n < 8; n++) {
                int d00 = diffb + j0 + 8 * n;
                int tl = tlb + 8 * n;
                if (d00 >= 2)     sacc[n].x += rp0[tl];
                if (d00 + 1 >= 2) sacc[n].y += rp0[tl + 1];
                if (d00 - 8 >= 2) sacc[n].z += rp1[tl - 8];
                if (d00 - 7 >= 2) sacc[n].w += rp1[tl - 7];
            }
            __syncwarp();
        }

        // ---- scale + online softmax ----
        float mx0 = -1e30f, mx1 = -1e30f;
        #pragma unroll
        for (int n = 0; n < 8; n++) {
            sacc[n].x *= SCALE; sacc[n].y *= SCALE;
            sacc[n].z *= SCALE; sacc[n].w *= SCALE;
            mx0 = fmaxf(mx0, fmaxf(sacc[n].x, sacc[n].y));
            mx1 = fmaxf(mx1, fmaxf(sacc[n].z, sacc[n].w));
        }
        #pragma unroll
        for (int off = 1; off <= 2; off <<= 1) {
            mx0 = fmaxf(mx0, __shfl_xor_sync(0xffffffffu, mx0, off));
            mx1 = fmaxf(mx1, __shfl_xor_sync(0xffffffffu, mx1, off));
        }
        float mn0 = fmaxf(m0r, mx0), mn1 = fmaxf(m1r, mx1);
        float c0 = __expf(m0r - mn0), c1 = __expf(m1r - mn1);
        float rs0 = 0.f, rs1 = 0.f;
        #pragma unroll
        for (int n = 0; n < 8; n++) {
            sacc[n].x = __expf(sacc[n].x - mn0);
            sacc[n].y = __expf(sacc[n].y - mn0);
            sacc[n].z = __expf(sacc[n].z - mn1);
            sacc[n].w = __expf(sacc[n].w - mn1);
            rs0 += sacc[n].x + sacc[n].y;
            rs1 += sacc[n].z + sacc[n].w;
        }
        #pragma unroll
        for (int off = 1; off <= 2; off <<= 1) {
            rs0 += __shfl_xor_sync(0xffffffffu, rs0, off);
            rs1 += __shfl_xor_sync(0xffffffffu, rs1, off);
        }
        l0r = l0r * c0 + rs0;  m0r = mn0;
        l1r = l1r * c1 + rs1;  m1r = mn1;
        #pragma unroll
        for (int n = 0; n < 8; n++) {
            Oacc[n].x *= c0; Oacc[n].y *= c0;
            Oacc[n].z *= c1; Oacc[n].w *= c1;
        }

        // ---- stage P (tf32 bits, warp-private rows) ----
        #pragma unroll
        for (int n = 0; n < 8; n++) {
            Pb0[8 * n + 2 * t]     = f2tf(sacc[n].x);
            Pb0[8 * n + 2 * t + 1] = f2tf(sacc[n].y);
            Pb1[8 * n + 2 * t]     = f2tf(sacc[n].z);
            Pb1[8 * n + 2 * t + 1] = f2tf(sacc[n].w);
        }
        __syncwarp();

        // ---- O += P V  (tf32 single-pass, 64 mma) ----
        #pragma unroll
        for (int sp = 0; sp < 8; sp++) {
            unsigned a0 = Pb0[8 * sp + t];
            unsigned a1 = Pb1[8 * sp + t];
            unsigned a2 = Pb0[8 * sp + t + 4];
            unsigned a3 = Pb1[8 * sp + t + 4];
            #pragma unroll
            for (int n = 0; n < 8; n++) {
                unsigned b0 = Vsu[(8 * sp + t) * VP + 8 * n + g];
                unsigned b1 = Vsu[(8 * sp + t + 4) * VP + 8 * n + g];
                mma8(Oacc[n], a0, a1, a2, a3, b0, b1);
            }
        }
        __syncwarp();
    }

    // ---- normalize + write out [b][s][h*64+d] ----
    const int b_ = bh >> 3, h = bh & 7;
    const float inv0 = 1.0f / l0r, inv1 = 1.0f / l1r;
    float* op0 = out + ((size_t)b_ * SS + (i0 + rbase + g)) * EE + h * HD;
    float* op1 = out + ((size_t)b_ * SS + (i0 + rbase + g + 8)) * EE + h * HD;
    #pragma unroll
    for (int n = 0; n < 8; n++) {
        *(float2*)&op0[8 * n + 2 * t] = make_float2(Oacc[n].x * inv0, Oacc[n].y * inv0);
        *(float2*)&op1[8 * n + 2 * t] = make_float2(Oacc[n].z * inv1, Oacc[n].w * inv1);
    }
}

// ---------------------------------------------------------------------------
// Kernel 3: in-place LayerNorm — one warp per row, pure shuffle reduction.
// ---------------------------------------------------------------------------
__global__ void __launch_bounds__(256) ln_kernel(
    float* __restrict__ out,
    const float* __restrict__ gamma,
    const float* __restrict__ beta)
{
    const int tid = threadIdx.x;
    const int lane = tid & 31, warp = tid >> 5;
    const int row = blockIdx.x * 8 + warp;
    float* p = out + (size_t)row * EE;

    float4 v[4];
    float s = 0.f, q = 0.f;
    #pragma unroll
    for (int k = 0; k < 4; k++) {
        v[k] = *(const float4*)&p[k * 128 + lane * 4];
        s += v[k].x + v[k].y + v[k].z + v[k].w;
        q += v[k].x * v[k].x + v[k].y * v[k].y + v[k].z * v[k].z + v[k].w * v[k].w;
    }
    #pragma unroll
    for (int off = 16; off > 0; off >>= 1) {
        s += __shfl_xor_sync(0xffffffffu, s, off);
        q += __shfl_xor_sync(0xffffffffu, q, off);
    }

    float mu = s * (1.0f / EE);
    float var = q * (1.0f / EE) - mu * mu;
    float inv = rsqrtf(var + 1e-5f);
    #pragma unroll
    for (int k = 0; k < 4; k++) {
        float4 gm = *(const float4*)&gamma[k * 128 + lane * 4];
        float4 bt = *(const float4*)&beta[k * 128 + lane * 4];
        float4 r;
        r.x = (v[k].x - mu) * inv * gm.x + bt.x;
        r.y = (v[k].y - mu) * inv * gm.y + bt.y;
        r.z = (v[k].z - mu) * inv * gm.z + bt.z;
        r.w = (v[k].w - mu) * inv * gm.w + bt.w;
        *(float4*)&p[k * 128 + lane * 4] = r;
    }
}

// ---------------------------------------------------------------------------
extern "C" void kernel_launch(void* const* d_in, const int* in_sizes, int n_in,
                              void* d_out, int out_size)
{
    const float* x     = (const float*)d_in[0];
    const float* Wq    = (const float*)d_in[1];
    const float* Wk    = (const float*)d_in[2];
    const float* Wv    = (const float*)d_in[3];
    const float* Er    = (const float*)d_in[4];
    const float* gamma = (const float*)d_in[5];
    const float* beta  = (const float*)d_in[6];
    float* out = (float*)d_out;

    cudaFuncSetAttribute(qkv_kernel, cudaFuncAttributeMaxDynamicSharedMemorySize, QKV_SMEM_BYTES);
    cudaFuncSetAttribute(attn_kernel, cudaFuncAttributeMaxDynamicSharedMemorySize, SMEM_BYTES);

    qkv_kernel<<<dim3(EE / 128, (BB * SS) / 128, 4), 256, QKV_SMEM_BYTES>>>(x, Wq, Wk, Wv, Er);
    attn_kernel<<<dim3(SS / 64, BB * HH), 128, SMEM_BYTES>>>(out);
    ln_kernel<<<BB * SS / 8, 256>>>(out, gamma, beta);
}